// round 17
// baseline (speedup 1.0000x reference)
#include <cuda_runtime.h>
#include <stdint.h>

// Problem constants (fixed: IM_SIZE=(1080,1920), SCALE=(0.25,0.25), B=8, C=3)
#define H_IN 1080
#define W_IN 1920
#define OH   270
#define OW   480
#define BC   24
#define MAX_TAPS 20
#define WQ   (W_IN / 4)

// Scratch for the generic (taps != 16) fallback path only.
__device__ float g_mid[(size_t)BC * OH * W_IN];

// ---------------------------------------------------------------------------
// FUSED kernel (taps==16): vertical resample inline + warp-shuffle horizontal.
// No mid array, no smem row, no block barriers in the row loop.
//
// Warp-chunk ww covers outputs [28*ww, 28*ww+27]. Lane L owns mid float4
// column c = 28*ww + L - 2 (clamped): it computes that column's vertical
// result v with 16 LDG.128+FMA, then 16 shuffles assemble the horizontal
// window cols [4*ow-6, 4*ow+9] for the 28 compute lanes. Mirror-edge lanes
// (ow in {0,1,478,479}) recompute via 16x16 scalar double-resample (L1-hot).
// Vertical weight/row tables for the block's R_F rows staged in smem once.
// grid: (2, OH/R_F, BC), block: 288 (9 warps)
// ---------------------------------------------------------------------------
#define R_F      9                    // rows per warp; 270 % 9 == 0
#define WARPS_PB 9
#define OUTS_PW  28

__global__ void __launch_bounds__(288, 3)
fused_shfl(const float* __restrict__ x,
           const float* __restrict__ w_h,
           const int*   __restrict__ idx_h,
           const float* __restrict__ w_w,
           const int*   __restrict__ idx_w,
           float* __restrict__ out)
{
    __shared__ float swv[R_F * 16];
    __shared__ int   srv[R_F * 16];

    const int tid = threadIdx.x;
    const int wid = tid >> 5;
    const int L   = tid & 31;
    const int ww  = blockIdx.x * WARPS_PB + wid;      // 0..17
    const int ow  = ww * OUTS_PW + L - 2;
    const int bc  = blockIdx.z;
    const int oh0 = blockIdx.y * R_F;

    // Stage vertical weights/rows for this block's R_F output rows
    for (int i = tid; i < R_F * 16; i += 288) {
        const int g = i >> 4;
        const int p = i & 15;
        swv[i] = w_h[(oh0 + g) * 16 + p];
        int r = idx_h[(oh0 + g) * 16 + p];
        r = (r < 0) ? 0 : (r > H_IN - 1 ? H_IN - 1 : r);
        srv[i] = r;
    }

    const int owc = (ow < 0) ? 0 : (ow > OW - 1 ? OW - 1 : ow);

    // Horizontal weights (kept in regs); conformance checked with temporaries.
    float wreg[16];
    bool conforms;
    {
        const float4* wp = (const float4*)(w_w + owc * 16);
        const int4*   ip = (const int4*)(idx_w + owc * 16);
        int c0 = 0;
        conforms = true;
#pragma unroll
        for (int j = 0; j < 4; ++j) {
            float4 wv = __ldg(wp + j);
            int4   iv = __ldg(ip + j);
            wreg[4 * j + 0] = wv.x; wreg[4 * j + 1] = wv.y;
            wreg[4 * j + 2] = wv.z; wreg[4 * j + 3] = wv.w;
            if (j == 0) c0 = iv.x;
            conforms = conforms && (iv.x == c0 + 4 * j)
                                && (iv.y == c0 + 4 * j + 1)
                                && (iv.z == c0 + 4 * j + 2)
                                && (iv.w == c0 + 4 * j + 3);
        }
        conforms = conforms && (c0 == 4 * ow - 6);
    }
    const bool compute = (L >= 2) && (L <= 29) && (ow < OW);
    const bool useShfl = compute && conforms;

    __syncthreads();                   // swv/srv visible (once, outside row loop)

    const float4* xcol = (const float4*)x + (size_t)bc * H_IN * WQ + owc;
    const float*  xrow = x + (size_t)bc * H_IN * W_IN;

#pragma unroll
    for (int r = 0; r < R_F; ++r) {
        // Vertical resample of this lane's float4 column (16 LDG.128, high MLP)
        float4 v = make_float4(0.f, 0.f, 0.f, 0.f);
#pragma unroll
        for (int p = 0; p < 16; ++p) {
            const float  w = swv[r * 16 + p];
            const float4 q = __ldg(xcol + (size_t)srv[r * 16 + p] * WQ);
            v.x += w * q.x; v.y += w * q.y; v.z += w * q.z; v.w += w * q.w;
        }

        // Warp-wide horizontal window exchange (unconditional, full mask)
        float4 am2, am1, ap1, ap2;
        am2.x = __shfl_up_sync(0xFFFFFFFFu, v.x, 2);
        am2.y = __shfl_up_sync(0xFFFFFFFFu, v.y, 2);
        am2.z = __shfl_up_sync(0xFFFFFFFFu, v.z, 2);
        am2.w = __shfl_up_sync(0xFFFFFFFFu, v.w, 2);
        am1.x = __shfl_up_sync(0xFFFFFFFFu, v.x, 1);
        am1.y = __shfl_up_sync(0xFFFFFFFFu, v.y, 1);
        am1.z = __shfl_up_sync(0xFFFFFFFFu, v.z, 1);
        am1.w = __shfl_up_sync(0xFFFFFFFFu, v.w, 1);
        ap1.x = __shfl_down_sync(0xFFFFFFFFu, v.x, 1);
        ap1.y = __shfl_down_sync(0xFFFFFFFFu, v.y, 1);
        ap1.z = __shfl_down_sync(0xFFFFFFFFu, v.z, 1);
        ap1.w = __shfl_down_sync(0xFFFFFFFFu, v.w, 1);
        ap2.x = __shfl_down_sync(0xFFFFFFFFu, v.x, 2);
        ap2.y = __shfl_down_sync(0xFFFFFFFFu, v.y, 2);
        ap2.z = __shfl_down_sync(0xFFFFFFFFu, v.z, 2);
        ap2.w = __shfl_down_sync(0xFFFFFFFFu, v.w, 2);

        if (compute) {
            float o;
            if (useShfl) {
                // window[2..17] of [am2|am1|v|ap1|ap2] = cols [4ow-6, 4ow+9]
                float a0 = 0.f, a1 = 0.f;
                a0 += wreg[0]  * am2.z;  a1 += wreg[1]  * am2.w;
                a0 += wreg[2]  * am1.x;  a1 += wreg[3]  * am1.y;
                a0 += wreg[4]  * am1.z;  a1 += wreg[5]  * am1.w;
                a0 += wreg[6]  * v.x;    a1 += wreg[7]  * v.y;
                a0 += wreg[8]  * v.z;    a1 += wreg[9]  * v.w;
                a0 += wreg[10] * ap1.x;  a1 += wreg[11] * ap1.y;
                a0 += wreg[12] * ap1.z;  a1 += wreg[13] * ap1.w;
                a0 += wreg[14] * ap2.x;  a1 += wreg[15] * ap2.y;
                o = a0 + a1;
            } else {
                // Mirror-edge double resample: 16 taps x 16 vertical rows,
                // all from L1-hot edge columns. Only ~2 lanes in 2 of 18 warps.
                o = 0.f;
                const int* myidx = idx_w + ow * 16;
#pragma unroll 4
                for (int p = 0; p < 16; ++p) {
                    int c = __ldg(myidx + p);
                    c = (c < 0) ? 0 : (c > W_IN - 1 ? W_IN - 1 : c);
                    float s = 0.f;
#pragma unroll
                    for (int q = 0; q < 16; ++q)
                        s += swv[r * 16 + q] *
                             __ldg(xrow + (size_t)srv[r * 16 + q] * W_IN + c);
                    o += wreg[p] * s;
                }
            }
            out[((size_t)bc * OH + oh0 + r) * OW + ow] = o;
        }
    }
}

// ---------------------------------------------------------------------------
// Generic fallback path (taps != 16): proven two-pass pipeline.
// ---------------------------------------------------------------------------
__global__ void __launch_bounds__(128)
pass1_generic(const float* __restrict__ x,
              const float* __restrict__ w_h,
              const int* __restrict__ idx_h,
              int taps)
{
    __shared__ float sw[MAX_TAPS];
    __shared__ int   srow[MAX_TAPS];

    const int oh = blockIdx.y;
    const int bc = blockIdx.z;
    const int t  = threadIdx.x;

    if (t < taps) {
        sw[t] = w_h[oh * taps + t];
        int r = idx_h[oh * taps + t];
        r = (r < 0) ? 0 : (r > H_IN - 1 ? H_IN - 1 : r);
        srow[t] = r;
    }
    __syncthreads();

    const int wq = blockIdx.x * 128 + t;
    if (wq >= WQ) return;

    const float4* xin = (const float4*)x + (size_t)bc * H_IN * WQ + wq;
    float4 acc = make_float4(0.f, 0.f, 0.f, 0.f);
    for (int p = 0; p < taps; ++p) {
        const float  w = sw[p];
        const float4 v = __ldg(xin + (size_t)srow[p] * WQ);
        acc.x += w * v.x; acc.y += w * v.y; acc.z += w * v.z; acc.w += w * v.w;
    }
    ((float4*)g_mid)[((size_t)bc * OH + oh) * WQ + wq] = acc;
}

#define R_ROWS2 9
#define SROW_SZ (W_IN + W_IN / 32)

__global__ void __launch_bounds__(480)
pass2_generic(const float* __restrict__ w_w,
              const int* __restrict__ idx_w,
              float* __restrict__ out,
              int taps)
{
    __shared__ float buf[2][SROW_SZ];

    const int t   = threadIdx.x;
    const int bc  = blockIdx.z;
    const int oh0 = blockIdx.y * R_ROWS2;

    float wreg[MAX_TAPS];
    int   preg[MAX_TAPS];
    for (int p = 0; p < taps; ++p) {
        wreg[p] = w_w[t * taps + p];
        int c = idx_w[t * taps + p];
        c = (c < 0) ? 0 : (c > W_IN - 1 ? W_IN - 1 : c);
        preg[p] = c + (c >> 5);
    }

    const int c0   = t * 4;
    const int base = c0 + (c0 >> 5);
    const float4* rows = (const float4*)g_mid + ((size_t)bc * OH + oh0) * WQ + t;

    float4 v = __ldg(rows);
    for (int r = 0; r < R_ROWS2; ++r) {
        float* cur = buf[r & 1];
        cur[base + 0] = v.x; cur[base + 1] = v.y;
        cur[base + 2] = v.z; cur[base + 3] = v.w;
        __syncthreads();
        if (r + 1 < R_ROWS2)
            v = __ldg(rows + (size_t)(r + 1) * WQ);
        float acc = 0.f;
        for (int p = 0; p < taps; ++p)
            acc += wreg[p] * cur[preg[p]];
        out[((size_t)bc * OH + oh0 + r) * OW + t] = acc;
    }
}

// ---------------------------------------------------------------------------
// kernel_launch
// inputs: x(f32), w_h(f32), idx_h(i32), w_w(f32), idx_w(i32); output f32
// ---------------------------------------------------------------------------
extern "C" void kernel_launch(void* const* d_in, const int* in_sizes, int n_in,
                              void* d_out, int out_size)
{
    const float* x     = (const float*)d_in[0];
    const float* w_h   = (const float*)d_in[1];
    const int*   idx_h = (const int*)d_in[2];
    const float* w_w   = (const float*)d_in[3];
    const int*   idx_w = (const int*)d_in[4];
    float*       out   = (float*)d_out;

    int taps_h = in_sizes[1] / OH;
    int taps_w = in_sizes[3] / OW;

    if (taps_h == 16 && taps_w == 16) {
        dim3 grid(2, OH / R_F, BC);            // (2, 30, 24) = 1440 blocks
        fused_shfl<<<grid, 288>>>(x, w_h, idx_h, w_w, idx_w, out);
    } else {
        if (taps_h > MAX_TAPS) taps_h = MAX_TAPS;
        if (taps_w > MAX_TAPS) taps_w = MAX_TAPS;
        dim3 g1((WQ + 127) / 128, OH, BC);
        pass1_generic<<<g1, 128>>>(x, w_h, idx_h, taps_h);
        dim3 g2(1, OH / R_ROWS2, BC);
        pass2_generic<<<g2, 480>>>(w_w, idx_w, out, taps_w);
    }
}